// round 11
// baseline (speedup 1.0000x reference)
#include <cuda_runtime.h>

// RoIAlign matching the JAX reference.
//   features: (B=2, C=256, H=200, W=200) fp32
//   rois:     (N=512, 5)  [batch_idx, x1, y1, x2, y2] image coords
//   out:      (N, C, 7, 7) fp32
//
// R6: staged-smem design (R5) with a fixed, vectorized loader:
//  - window rows loaded as float4 (alignment-adjusted, right-edge safe),
//    2 rows per warp-iteration, no integer divides in the loop
//  - per-thread (offset,weight) pairs computed once per block, offsets
//    packed two-per-register
//  - compute = 16 LDS + 16 FFMA per output

#define POOLED 7
#define SPATIAL_SCALE 0.0625f
#define CPR 5                      // channels staged per round
#define SEG 8                      // channel segments per roi (256/8 = 32)
#define THREADS 256
#define ROWS_MAX 43
#define WS4 13                     // smem row stride in float4 (52 floats)
#define WSF (WS4 * 4)
#define WIN_F4 (ROWS_MAX * WS4)    // 559 float4 per channel window
#define WIN_FLOATS (WIN_F4 * 4)    // 2236 floats

__global__ __launch_bounds__(THREADS)
void roi_align_kernel(const float* __restrict__ feat,
                      const float* __restrict__ rois,
                      float* __restrict__ out,
                      int N, int C, int H, int W)
{
    __shared__ float4 win4[CPR * WIN_F4];          // ~44.7 KB

    const int HW = H * W;
    const int W4 = W >> 2;                          // 50
    const int cseg = C / SEG;                       // 32

    int n   = blockIdx.x / SEG;
    int seg = blockIdx.x % SEG;
    int t    = threadIdx.x;
    int warp = t >> 5;
    int lane = t & 31;
    int c_start = seg * cseg;
    int c_end   = c_start + cseg;

    const float* r = rois + n * 5;
    int   b  = (int)__ldg(r + 0);
    float x1 = __ldg(r + 1) * SPATIAL_SCALE;
    float y1 = __ldg(r + 2) * SPATIAL_SCALE;
    float x2 = __ldg(r + 3) * SPATIAL_SCALE;
    float y2 = __ldg(r + 4) * SPATIAL_SCALE;

    float bin_w = fmaxf(x2 - x1, 1.0f) * (1.0f / POOLED);
    float bin_h = fmaxf(y2 - y1, 1.0f) * (1.0f / POOLED);

    // ---- window extent (samples monotonic in ph/iy: first +0.25b, last +6.75b) ----
    float yS0 = y1 + 0.25f * bin_h;
    float ySM = y1 + 6.75f * bin_h;
    int row0  = min((int)fmaxf(yS0, 0.0f), H - 1);
    int ylM   = min((int)fmaxf(ySM, 0.0f), H - 1);
    int rowL  = min(ylM + 1, H - 1);
    int rows  = rowL - row0 + 1;                    // <= 43

    float xS0 = x1 + 0.25f * bin_w;
    float xSM = x1 + 6.75f * bin_w;
    int col0  = min((int)fmaxf(xS0, 0.0f), W - 1);
    int xlM   = min((int)fmaxf(xSM, 0.0f), W - 1);
    int colL  = min(xlM + 1, W - 1);

    // x alignment for float4 loads; keep the last float4 inside the row
    int col0a = col0 & ~3;
    int nf4   = (colL - col0a + 4) >> 2;            // <= 12, covers [col0, colL]
    if (col0a + nf4 * 4 > W) col0a = W - nf4 * 4;   // coverage preserved (see R6 notes)
    int c04 = col0a >> 2;

    // ---- per-thread pooled position; 16 (offset,weight) pairs in registers ----
    int cl = t / 49;                                 // channel slot (5 -> loader-only)
    int p  = t % 49;
    int ph = p / POOLED;
    int pw = p % POOLED;

    int   poff[8];                                   // packed pairs of 12-bit offsets
    float wgt[16];
    {
        int offl[16];
        #pragma unroll
        for (int iy = 0; iy < 2; iy++) {
            float yc = y1 + ((float)ph + 0.25f + 0.5f * (float)iy) * bin_h;
            bool  vy = (yc >= -1.0f) && (yc <= (float)H);
            float cy = fmaxf(yc, 0.0f);
            int   yl = min((int)cy, H - 1);
            int   yh = min(yl + 1, H - 1);
            float fy = (yl >= H - 1) ? 0.0f : (cy - (float)yl);

            #pragma unroll
            for (int ix = 0; ix < 2; ix++) {
                float xc = x1 + ((float)pw + 0.25f + 0.5f * (float)ix) * bin_w;
                bool  vx = (xc >= -1.0f) && (xc <= (float)W);
                float cx = fmaxf(xc, 0.0f);
                int   xl = min((int)cx, W - 1);
                int   xh = min(xl + 1, W - 1);
                float fx = (xl >= W - 1) ? 0.0f : (cx - (float)xl);

                float wv = (vy && vx) ? 0.25f : 0.0f;
                int k  = (iy * 2 + ix) * 4;
                int rl = (yl - row0) * WSF - col0a;
                int rh = (yh - row0) * WSF - col0a;
                offl[k + 0] = rl + xl;  wgt[k + 0] = wv * (1.0f - fy) * (1.0f - fx);
                offl[k + 1] = rl + xh;  wgt[k + 1] = wv * (1.0f - fy) * fx;
                offl[k + 2] = rh + xl;  wgt[k + 2] = wv * fy * (1.0f - fx);
                offl[k + 3] = rh + xh;  wgt[k + 3] = wv * fy * fx;
            }
        }
        #pragma unroll
        for (int j = 0; j < 8; j++)
            poff[j] = offl[2 * j] | (offl[2 * j + 1] << 16);
    }

    // loader lane roles: two rows per warp-iteration
    int sub = lane >> 4;                             // 0 or 1 (row pair)
    int lx  = lane & 15;                             // float4 index in row
    const float4* fsrc = (const float4*)feat
                       + ((size_t)b * C) * (size_t)(HW >> 2)
                       + (size_t)row0 * W4 + c04;

    // ---- channel rounds ----
    for (int c0 = c_start; c0 < c_end; c0 += CPR) {
        // stage up to CPR channel windows (coalesced float4 row loads)
        #pragma unroll
        for (int ch = 0; ch < CPR; ch++) {
            int cw = c0 + ch;
            if (cw >= c_end) break;
            const float4* src = fsrc + (size_t)cw * (size_t)(HW >> 2);
            float4* dst = win4 + ch * WIN_F4;
            if (lx < nf4) {
                for (int rr = warp * 2 + sub; rr < rows; rr += 16)
                    dst[rr * WS4 + lx] = __ldg(src + (size_t)rr * W4 + lx);
            }
        }
        __syncthreads();

        int c = c0 + cl;
        if (cl < CPR && c < c_end) {
            const float* wb = (const float*)win4 + cl * WIN_FLOATS;
            float acc = 0.0f;
            #pragma unroll
            for (int j = 0; j < 8; j++) {
                int o0 = poff[j] & 0xFFFF;
                int o1 = poff[j] >> 16;
                acc += wgt[2 * j] * wb[o0];
                acc += wgt[2 * j + 1] * wb[o1];
            }
            out[((size_t)n * C + c) * 49 + p] = acc;
        }
        __syncthreads();
    }
}

extern "C" void kernel_launch(void* const* d_in, const int* in_sizes, int n_in,
                              void* d_out, int out_size)
{
    const float* feat = (const float*)d_in[0];   // (2,256,200,200) fp32
    const float* rois = (const float*)d_in[1];   // (512,5) fp32
    float* out = (float*)d_out;                  // (512,256,7,7) fp32

    const int C = 256, H = 200, W = 200;
    int N = in_sizes[1] / 5;
    (void)n_in; (void)out_size;

    int blocks = N * SEG;
    roi_align_kernel<<<blocks, THREADS>>>(feat, rois, out, N, C, H, W);
}

// round 12
// speedup vs baseline: 1.0130x; 1.0130x over previous
#include <cuda_runtime.h>

// RoIAlign matching the JAX reference.
//   features: (B=2, C=256, H=200, W=200) fp32
//   rois:     (N=512, 5)  [batch_idx, x1, y1, x2, y2] image coords
//   out:      (N, C, 7, 7) fp32
//
// R6: staged-smem design (R5) with a fixed, vectorized loader:
//  - window rows loaded as float4 (alignment-adjusted, right-edge safe),
//    2 rows per warp-iteration, no integer divides in the loop
//  - per-thread (offset,weight) pairs computed once per block, offsets
//    packed two-per-register
//  - compute = 16 LDS + 16 FFMA per output

#define POOLED 7
#define SPATIAL_SCALE 0.0625f
#define CPR 5                      // channels staged per round
#define SEG 8                      // channel segments per roi (256/8 = 32)
#define THREADS 256
#define ROWS_MAX 43
#define WS4 13                     // smem row stride in float4 (52 floats)
#define WSF (WS4 * 4)
#define WIN_F4 (ROWS_MAX * WS4)    // 559 float4 per channel window
#define WIN_FLOATS (WIN_F4 * 4)    // 2236 floats

__global__ __launch_bounds__(THREADS)
void roi_align_kernel(const float* __restrict__ feat,
                      const float* __restrict__ rois,
                      float* __restrict__ out,
                      int N, int C, int H, int W)
{
    __shared__ float4 win4[CPR * WIN_F4];          // ~44.7 KB

    const int HW = H * W;
    const int W4 = W >> 2;                          // 50
    const int cseg = C / SEG;                       // 32

    int n   = blockIdx.x / SEG;
    int seg = blockIdx.x % SEG;
    int t    = threadIdx.x;
    int warp = t >> 5;
    int lane = t & 31;
    int c_start = seg * cseg;
    int c_end   = c_start + cseg;

    const float* r = rois + n * 5;
    int   b  = (int)__ldg(r + 0);
    float x1 = __ldg(r + 1) * SPATIAL_SCALE;
    float y1 = __ldg(r + 2) * SPATIAL_SCALE;
    float x2 = __ldg(r + 3) * SPATIAL_SCALE;
    float y2 = __ldg(r + 4) * SPATIAL_SCALE;

    float bin_w = fmaxf(x2 - x1, 1.0f) * (1.0f / POOLED);
    float bin_h = fmaxf(y2 - y1, 1.0f) * (1.0f / POOLED);

    // ---- window extent (samples monotonic in ph/iy: first +0.25b, last +6.75b) ----
    float yS0 = y1 + 0.25f * bin_h;
    float ySM = y1 + 6.75f * bin_h;
    int row0  = min((int)fmaxf(yS0, 0.0f), H - 1);
    int ylM   = min((int)fmaxf(ySM, 0.0f), H - 1);
    int rowL  = min(ylM + 1, H - 1);
    int rows  = rowL - row0 + 1;                    // <= 43

    float xS0 = x1 + 0.25f * bin_w;
    float xSM = x1 + 6.75f * bin_w;
    int col0  = min((int)fmaxf(xS0, 0.0f), W - 1);
    int xlM   = min((int)fmaxf(xSM, 0.0f), W - 1);
    int colL  = min(xlM + 1, W - 1);

    // x alignment for float4 loads; keep the last float4 inside the row
    int col0a = col0 & ~3;
    int nf4   = (colL - col0a + 4) >> 2;            // <= 12, covers [col0, colL]
    if (col0a + nf4 * 4 > W) col0a = W - nf4 * 4;   // coverage preserved (see R6 notes)
    int c04 = col0a >> 2;

    // ---- per-thread pooled position; 16 (offset,weight) pairs in registers ----
    int cl = t / 49;                                 // channel slot (5 -> loader-only)
    int p  = t % 49;
    int ph = p / POOLED;
    int pw = p % POOLED;

    int   poff[8];                                   // packed pairs of 12-bit offsets
    float wgt[16];
    {
        int offl[16];
        #pragma unroll
        for (int iy = 0; iy < 2; iy++) {
            float yc = y1 + ((float)ph + 0.25f + 0.5f * (float)iy) * bin_h;
            bool  vy = (yc >= -1.0f) && (yc <= (float)H);
            float cy = fmaxf(yc, 0.0f);
            int   yl = min((int)cy, H - 1);
            int   yh = min(yl + 1, H - 1);
            float fy = (yl >= H - 1) ? 0.0f : (cy - (float)yl);

            #pragma unroll
            for (int ix = 0; ix < 2; ix++) {
                float xc = x1 + ((float)pw + 0.25f + 0.5f * (float)ix) * bin_w;
                bool  vx = (xc >= -1.0f) && (xc <= (float)W);
                float cx = fmaxf(xc, 0.0f);
                int   xl = min((int)cx, W - 1);
                int   xh = min(xl + 1, W - 1);
                float fx = (xl >= W - 1) ? 0.0f : (cx - (float)xl);

                float wv = (vy && vx) ? 0.25f : 0.0f;
                int k  = (iy * 2 + ix) * 4;
                int rl = (yl - row0) * WSF - col0a;
                int rh = (yh - row0) * WSF - col0a;
                offl[k + 0] = rl + xl;  wgt[k + 0] = wv * (1.0f - fy) * (1.0f - fx);
                offl[k + 1] = rl + xh;  wgt[k + 1] = wv * (1.0f - fy) * fx;
                offl[k + 2] = rh + xl;  wgt[k + 2] = wv * fy * (1.0f - fx);
                offl[k + 3] = rh + xh;  wgt[k + 3] = wv * fy * fx;
            }
        }
        #pragma unroll
        for (int j = 0; j < 8; j++)
            poff[j] = offl[2 * j] | (offl[2 * j + 1] << 16);
    }

    // loader lane roles: two rows per warp-iteration
    int sub = lane >> 4;                             // 0 or 1 (row pair)
    int lx  = lane & 15;                             // float4 index in row
    const float4* fsrc = (const float4*)feat
                       + ((size_t)b * C) * (size_t)(HW >> 2)
                       + (size_t)row0 * W4 + c04;

    // ---- channel rounds ----
    for (int c0 = c_start; c0 < c_end; c0 += CPR) {
        // stage up to CPR channel windows (coalesced float4 row loads)
        #pragma unroll
        for (int ch = 0; ch < CPR; ch++) {
            int cw = c0 + ch;
            if (cw >= c_end) break;
            const float4* src = fsrc + (size_t)cw * (size_t)(HW >> 2);
            float4* dst = win4 + ch * WIN_F4;
            if (lx < nf4) {
                for (int rr = warp * 2 + sub; rr < rows; rr += 16)
                    dst[rr * WS4 + lx] = __ldg(src + (size_t)rr * W4 + lx);
            }
        }
        __syncthreads();

        int c = c0 + cl;
        if (cl < CPR && c < c_end) {
            const float* wb = (const float*)win4 + cl * WIN_FLOATS;
            float acc = 0.0f;
            #pragma unroll
            for (int j = 0; j < 8; j++) {
                int o0 = poff[j] & 0xFFFF;
                int o1 = poff[j] >> 16;
                acc += wgt[2 * j] * wb[o0];
                acc += wgt[2 * j + 1] * wb[o1];
            }
            out[((size_t)n * C + c) * 49 + p] = acc;
        }
        __syncthreads();
    }
}

extern "C" void kernel_launch(void* const* d_in, const int* in_sizes, int n_in,
                              void* d_out, int out_size)
{
    const float* feat = (const float*)d_in[0];   // (2,256,200,200) fp32
    const float* rois = (const float*)d_in[1];   // (512,5) fp32
    float* out = (float*)d_out;                  // (512,256,7,7) fp32

    const int C = 256, H = 200, W = 200;
    int N = in_sizes[1] / 5;
    (void)n_in; (void)out_size;

    int blocks = N * SEG;
    roi_align_kernel<<<blocks, THREADS>>>(feat, rois, out, N, C, H, W);
}